// round 2
// baseline (speedup 1.0000x reference)
#include <cuda_runtime.h>

#define NN 8
#define LL 6400
#define KK 100
#define CC 256
#define L2 (2*LL)

// Scratch (no allocations allowed) — all fully rewritten every launch.
__device__ float d_S[NN][2][KK];
__device__ int   d_ind0[NN];
__device__ int   d_rank[NN*LL];   // rank if selected, else -1
__device__ int   d_len[NN];

// ---------------------------------------------------------------- zero init
__global__ void tf_zero_kernel() {
    int t = threadIdx.x;
    float* s = &d_S[0][0][0];
    for (int i = t; i < NN*2*KK; i += blockDim.x) s[i] = 0.0f;
}

// -------------------------------------------------- column sums of prob_topics
// grid (64, NN), block 128 (threads >= KK idle). Chunks of 200 rows, aligned to
// the half boundary (6400 = 32*200), so each block touches exactly one half.
__global__ void tf_reduce_kernel(const float* __restrict__ prob) {
    int n = blockIdx.y;
    int chunk = blockIdx.x;
    int k = threadIdx.x;
    if (k >= KK) return;
    int row0 = chunk * 200;
    int h = (row0 >= LL) ? 1 : 0;
    const float* base = prob + ((size_t)n * L2 + row0) * KK + k;
    float acc = 0.0f;
    #pragma unroll 8
    for (int r = 0; r < 200; r++) acc += __ldg(base + (size_t)r * KK);
    atomicAdd(&d_S[n][h][k], acc);
}

// -------------------------------------------------- argmax_k S0[k]*S1[k]
// top_k tie-break = lowest index first; strict-greater + prefer-lower-index.
__global__ void tf_argmax_kernel() {
    int n = blockIdx.x;
    int t = threadIdx.x;            // 128
    __shared__ float bv[128];
    __shared__ int   bi[128];
    float best = -1.0f; int bidx = KK;
    if (t < KK) { best = d_S[n][0][t] * d_S[n][1][t]; bidx = t; }
    bv[t] = best; bi[t] = bidx;
    __syncthreads();
    for (int s = 64; s > 0; s >>= 1) {
        if (t < s) {
            if (bv[t+s] > bv[t] || (bv[t+s] == bv[t] && bi[t+s] < bi[t])) {
                bv[t] = bv[t+s]; bi[t] = bi[t+s];
            }
        }
        __syncthreads();
    }
    if (t == 0) d_ind0[n] = bi[0];
}

// -------------------------------------------------- mask + exclusive scan per n
// grid NN, block 256; each thread owns 25 consecutive l. Also writes new_mask.
__global__ void tf_scan_kernel(const float* __restrict__ topics,
                               float* __restrict__ out_mask) {
    int n = blockIdx.x;
    int t = threadIdx.x;            // 256
    const int CH = LL / 256;        // 25
    int ind = d_ind0[n];
    const float* tp = topics + (size_t)n * L2 * KK + ind;
    int l0 = t * CH;

    unsigned bits = 0;
    int sum = 0;
    #pragma unroll
    for (int i = 0; i < CH; i++) {
        float v = __ldg(tp + (size_t)(l0 + i) * KK);
        if (v > 0.5f) { bits |= (1u << i); sum++; }
    }

    __shared__ int ps[256];
    ps[t] = sum;
    __syncthreads();
    // Hillis-Steele inclusive scan (read -> sync -> write -> sync)
    for (int off = 1; off < 256; off <<= 1) {
        int v = (t >= off) ? ps[t - off] : 0;
        __syncthreads();
        ps[t] += v;
        __syncthreads();
    }
    int excl  = ps[t] - sum;
    int total = ps[255];

    int r = excl;
    #pragma unroll
    for (int i = 0; i < CH; i++) {
        int l = l0 + i;
        int m = (bits >> i) & 1;
        d_rank[n*LL + l] = m ? r : -1;
        r += m;
        out_mask[n*LL + l] = (l < total) ? 1.0f : 0.0f;
    }
    if (t == 0) d_len[n] = total;
}

// -------------------------------------------------- compact + zero-fill
// grid (LL/4, NN), block (64,4). Each (warp-pair) row: 64 lanes x float4 = 256 f.
__global__ void tf_scatter_kernel(const float* __restrict__ feat,
                                  float* __restrict__ out) {
    int n = blockIdx.y;
    int l = blockIdx.x * blockDim.y + threadIdx.y;
    int t = threadIdx.x;            // 64
    int r   = d_rank[n*LL + l];
    int len = d_len[n];
    const float4* src = (const float4*)(feat + ((size_t)n*LL + l) * CC);
    if (r >= 0) {
        float4* dst = (float4*)(out + ((size_t)n*LL + r) * CC);
        dst[t] = src[t];
    }
    if (l >= len) {
        float4* dst = (float4*)(out + ((size_t)n*LL + l) * CC);
        dst[t] = make_float4(0.f, 0.f, 0.f, 0.f);
    }
}

extern "C" void kernel_launch(void* const* d_in, const int* in_sizes, int n_in,
                              void* d_out, int out_size) {
    const float* feat   = (const float*)d_in[0];   // (8, 6400, 256)
    const float* prob   = (const float*)d_in[1];   // (8, 12800, 100)
    const float* topics = (const float*)d_in[2];   // (8, 12800, 100)
    // d_in[3] = n_samples: only index 0 of top-k is consumed -> argmax; unused.

    float* out_feat = (float*)d_out;               // (8, 6400, 256)
    float* out_mask = out_feat + (size_t)NN*LL*CC; // (8, 6400)

    tf_zero_kernel<<<1, 256>>>();
    tf_reduce_kernel<<<dim3(64, NN), 128>>>(prob);
    tf_argmax_kernel<<<NN, 128>>>();
    tf_scan_kernel<<<NN, 256>>>(topics, out_mask);
    tf_scatter_kernel<<<dim3(LL/4, NN), dim3(64, 4)>>>(feat, out_feat);
}

// round 3
// speedup vs baseline: 1.2437x; 1.2437x over previous
#include <cuda_runtime.h>

#define NN 8
#define LL 6400
#define KK 100
#define CC 256
#define L2 (2*LL)
#define NCHUNK 25          // chunks of 256 l per n
#define NWORDS (NCHUNK*8)  // 200 ballot words per n

// Scratch (no allocations allowed) — fully rewritten every launch.
__device__ float    d_part[NN][64][KK];   // per-chunk column partial sums
__device__ int      d_ind0[NN];
__device__ unsigned d_bits[NN][NWORDS];   // selection bitmask, 32 l per word
__device__ int      d_rank[NN*LL];        // rank if selected, else -1
__device__ int      d_len[NN];

// -------------------------------------------- column partial sums (no atomics)
// grid (64, NN), block 128. Chunk = 200 rows; chunks 0..31 = half 0, 32..63 = half 1.
__global__ void tf_reduce_kernel(const float* __restrict__ prob) {
    int n = blockIdx.y;
    int chunk = blockIdx.x;
    int k = threadIdx.x;
    if (k >= KK) return;
    const float* base = prob + ((size_t)n * L2 + (size_t)chunk * 200) * KK + k;
    float acc = 0.0f;
    #pragma unroll 8
    for (int r = 0; r < 200; r++) acc += __ldg(base + (size_t)r * KK);
    d_part[n][chunk][k] = acc;
}

// -------------------------------------------- argmax_k S0[k]*S1[k]
// top_k tie-break = lowest index first -> strict-greater, prefer lower index.
__global__ void tf_argmax_kernel() {
    int n = blockIdx.x;
    int t = threadIdx.x;            // 128
    __shared__ float bv[128];
    __shared__ int   bi[128];
    float best = -1.0f; int bidx = KK;
    if (t < KK) {
        float s0 = 0.f, s1 = 0.f;
        #pragma unroll 8
        for (int c = 0; c < 32; c++) s0 += d_part[n][c][t];
        #pragma unroll 8
        for (int c = 32; c < 64; c++) s1 += d_part[n][c][t];
        best = s0 * s1; bidx = t;
    }
    bv[t] = best; bi[t] = bidx;
    __syncthreads();
    for (int s = 64; s > 0; s >>= 1) {
        if (t < s) {
            if (bv[t+s] > bv[t] || (bv[t+s] == bv[t] && bi[t+s] < bi[t])) {
                bv[t] = bv[t+s]; bi[t] = bi[t+s];
            }
        }
        __syncthreads();
    }
    if (t == 0) d_ind0[n] = bi[0];
}

// -------------------------------------------- gather + ballot (wide, 200 blocks)
// grid (NCHUNK, NN), block 256. One strided topics load per thread.
__global__ void tf_mask_kernel(const float* __restrict__ topics) {
    int n = blockIdx.y;
    int t = threadIdx.x;
    int l = blockIdx.x * 256 + t;
    int ind = d_ind0[n];
    float v = __ldg(topics + ((size_t)n * L2 + l) * KK + ind);
    unsigned ballot = __ballot_sync(0xFFFFFFFFu, v > 0.5f);
    if ((t & 31) == 0) d_bits[n][blockIdx.x * 8 + (t >> 5)] = ballot;
}

// -------------------------------------------- rank + mask from bitmask
// grid (NCHUNK, NN), block 256. Loads all 200 words into smem; each thread
// computes its exclusive popcount prefix + total length.
__global__ void tf_rank_kernel(float* __restrict__ out_mask) {
    int n = blockIdx.y;
    int t = threadIdx.x;
    __shared__ unsigned w[NWORDS];
    if (t < NWORDS) w[t] = d_bits[n][t];
    __syncthreads();

    int myword = blockIdx.x * 8 + (t >> 5);
    int lane = t & 31;
    int off = 0, tot = 0;
    #pragma unroll 8
    for (int j = 0; j < NWORDS; j++) {
        int p = __popc(w[j]);
        tot += p;
        if (j < myword) off += p;
    }
    unsigned word = w[myword];
    int rank = off + __popc(word & ((1u << lane) - 1u));
    int bit = (word >> lane) & 1;
    int l = blockIdx.x * 256 + t;
    d_rank[n*LL + l] = bit ? rank : -1;
    out_mask[n*LL + l] = (l < tot) ? 1.0f : 0.0f;
    if (blockIdx.x == 0 && t == 0) d_len[n] = tot;
}

// -------------------------------------------- compact + zero-fill
// grid (LL/4, NN), block (64,4). Each y-row: 64 lanes x float4 = 256 floats.
__global__ void tf_scatter_kernel(const float* __restrict__ feat,
                                  float* __restrict__ out) {
    int n = blockIdx.y;
    int l = blockIdx.x * blockDim.y + threadIdx.y;
    int t = threadIdx.x;            // 64
    int r   = d_rank[n*LL + l];
    int len = d_len[n];
    const float4* src = (const float4*)(feat + ((size_t)n*LL + l) * CC);
    if (r >= 0) {
        float4* dst = (float4*)(out + ((size_t)n*LL + r) * CC);
        dst[t] = src[t];
    }
    if (l >= len) {
        float4* dst = (float4*)(out + ((size_t)n*LL + l) * CC);
        dst[t] = make_float4(0.f, 0.f, 0.f, 0.f);
    }
}

extern "C" void kernel_launch(void* const* d_in, const int* in_sizes, int n_in,
                              void* d_out, int out_size) {
    const float* feat   = (const float*)d_in[0];   // (8, 6400, 256)
    const float* prob   = (const float*)d_in[1];   // (8, 12800, 100)
    const float* topics = (const float*)d_in[2];   // (8, 12800, 100)
    // d_in[3] = n_samples: only top-1 index is consumed -> argmax; unused here.

    float* out_feat = (float*)d_out;               // (8, 6400, 256)
    float* out_mask = out_feat + (size_t)NN*LL*CC; // (8, 6400)

    tf_reduce_kernel<<<dim3(64, NN), 128>>>(prob);
    tf_argmax_kernel<<<NN, 128>>>();
    tf_mask_kernel<<<dim3(NCHUNK, NN), 256>>>(topics);
    tf_rank_kernel<<<dim3(NCHUNK, NN), 256>>>(out_mask);
    tf_scatter_kernel<<<dim3(LL/4, NN), dim3(64, 4)>>>(feat, out_feat);
}

// round 4
// speedup vs baseline: 1.3471x; 1.0831x over previous
#include <cuda_runtime.h>

#define NN 8
#define LL 6400
#define KK 100
#define CC 256
#define L2 (2*LL)
#define NCHUNK 25          // chunks of 256 l per n
#define NWORDS (NCHUNK*8)  // 200 ballot words per n

// Scratch (no allocations allowed) — fully rewritten every launch.
__device__ float    d_part[NN][64][KK];   // per-chunk column partial sums
__device__ unsigned d_bits[NN][NWORDS];   // selection bitmask, 32 l per word
__device__ int      d_woff[NN][NWORDS];   // exclusive popcount prefix per word
__device__ int      d_len[NN];

// -------------------------------------------- column partial sums (no atomics)
// grid (64, NN), block 128. Chunk = 200 rows; chunks 0..31 = half 0, 32..63 = half 1.
__global__ void tf_reduce_kernel(const float* __restrict__ prob) {
    int n = blockIdx.y;
    int chunk = blockIdx.x;
    int k = threadIdx.x;
    if (k >= KK) return;
    const float* base = prob + ((size_t)n * L2 + (size_t)chunk * 200) * KK + k;
    float acc = 0.0f;
    #pragma unroll 8
    for (int r = 0; r < 200; r++) acc += __ldg(base + (size_t)r * KK);
    d_part[n][chunk][k] = acc;
}

// -------------------------------------------- fused argmax + gather + ballot
// grid (NCHUNK, NN), block 256. Every block redundantly computes the (fully
// deterministic) argmax_k S0[k]*S1[k] from L2-resident partials, then gathers
// its 256 topic values and ballots the selection mask.
// top_k tie-break = lowest index first -> strict-greater, prefer lower index.
__global__ void tf_maskargmax_kernel(const float* __restrict__ topics) {
    int n = blockIdx.y;
    int t = threadIdx.x;
    __shared__ float bv[128];
    __shared__ int   bi[128];
    __shared__ int   s_ind;

    if (t < 128) {
        float best = -1.0f; int bidx = KK;
        if (t < KK) {
            float s0 = 0.f, s1 = 0.f;
            #pragma unroll 8
            for (int c = 0; c < 32; c++) s0 += d_part[n][c][t];
            #pragma unroll 8
            for (int c = 32; c < 64; c++) s1 += d_part[n][c][t];
            best = s0 * s1; bidx = t;
        }
        bv[t] = best; bi[t] = bidx;
    }
    __syncthreads();
    for (int s = 64; s > 0; s >>= 1) {
        if (t < s) {
            if (bv[t+s] > bv[t] || (bv[t+s] == bv[t] && bi[t+s] < bi[t])) {
                bv[t] = bv[t+s]; bi[t] = bi[t+s];
            }
        }
        __syncthreads();
    }
    if (t == 0) s_ind = bi[0];
    __syncthreads();

    int ind = s_ind;
    int l = blockIdx.x * 256 + t;
    float v = __ldg(topics + ((size_t)n * L2 + l) * KK + ind);
    unsigned ballot = __ballot_sync(0xFFFFFFFFu, v > 0.5f);
    if ((t & 31) == 0) d_bits[n][blockIdx.x * 8 + (t >> 5)] = ballot;
}

// -------------------------------------------- word-offset scan + out_mask
// grid NN, block 256. Exclusive prefix of per-word popcounts (200 words),
// total length, and the (n, 6400) output mask.
__global__ void tf_woff_kernel(float* __restrict__ out_mask) {
    int n = blockIdx.x;
    int t = threadIdx.x;
    __shared__ int ps[256];
    int p = 0;
    if (t < NWORDS) p = __popc(d_bits[n][t]);
    ps[t] = p;
    __syncthreads();
    for (int off = 1; off < 256; off <<= 1) {
        int v = (t >= off) ? ps[t - off] : 0;
        __syncthreads();
        ps[t] += v;
        __syncthreads();
    }
    if (t < NWORDS) d_woff[n][t] = ps[t] - p;
    int tot = ps[NWORDS - 1];
    if (t == 0) d_len[n] = tot;

    float* m = out_mask + (size_t)n * LL;
    #pragma unroll
    for (int l = t; l < LL; l += 256) m[l] = (l < tot) ? 1.0f : 0.0f;
}

// -------------------------------------------- compact + zero-fill (inline rank)
// grid (LL/4, NN), block (64,4). Each y-row: 64 lanes x float4 = 256 floats.
__global__ void tf_scatter_kernel(const float* __restrict__ feat,
                                  float* __restrict__ out) {
    int n = blockIdx.y;
    int l = blockIdx.x * blockDim.y + threadIdx.y;
    int t = threadIdx.x;            // 64
    int w = l >> 5;
    int lane = l & 31;
    unsigned word = d_bits[n][w];           // broadcast, L2-resident
    int r = d_woff[n][w] + __popc(word & ((1u << lane) - 1u));
    int bit = (word >> lane) & 1;
    int len = d_len[n];
    const float4* src = (const float4*)(feat + ((size_t)n*LL + l) * CC);
    if (bit) {
        float4* dst = (float4*)(out + ((size_t)n*LL + r) * CC);
        dst[t] = src[t];
    }
    if (l >= len) {
        float4* dst = (float4*)(out + ((size_t)n*LL + l) * CC);
        dst[t] = make_float4(0.f, 0.f, 0.f, 0.f);
    }
}

extern "C" void kernel_launch(void* const* d_in, const int* in_sizes, int n_in,
                              void* d_out, int out_size) {
    const float* feat   = (const float*)d_in[0];   // (8, 6400, 256)
    const float* prob   = (const float*)d_in[1];   // (8, 12800, 100)
    const float* topics = (const float*)d_in[2];   // (8, 12800, 100)
    // d_in[3] = n_samples: only top-1 index is consumed -> argmax; unused here.

    float* out_feat = (float*)d_out;               // (8, 6400, 256)
    float* out_mask = out_feat + (size_t)NN*LL*CC; // (8, 6400)

    tf_reduce_kernel<<<dim3(64, NN), 128>>>(prob);
    tf_maskargmax_kernel<<<dim3(NCHUNK, NN), 256>>>(topics);
    tf_woff_kernel<<<NN, 256>>>(out_mask);
    tf_scatter_kernel<<<dim3(LL/4, NN), dim3(64, 4)>>>(feat, out_feat);
}

// round 5
// speedup vs baseline: 1.4194x; 1.0537x over previous
#include <cuda_runtime.h>

#define NN 8
#define LL 6400
#define KK 100
#define CC 256
#define L2 (2*LL)
#define NCHUNK 25          // chunks of 256 l per n
#define NWORDS (NCHUNK*8)  // 200 ballot words per n

// Scratch (no allocations allowed) — fully rewritten every launch.
__device__ float    d_part[NN][64][KK];   // per-chunk column partial sums
__device__ unsigned d_bits[NN][NWORDS];   // selection bitmask, 32 l per word
__device__ int      d_srcrow[NN][LL];     // inverse perm: dst rank -> src row
__device__ int      d_len[NN];

// -------------------------------------------- column partial sums (no atomics)
// grid (64, NN), block 128. Chunk = 200 rows; chunks 0..31 = half 0, 32..63 = half 1.
__global__ void tf_reduce_kernel(const float* __restrict__ prob) {
    int n = blockIdx.y;
    int chunk = blockIdx.x;
    int k = threadIdx.x;
    if (k >= KK) return;
    const float* base = prob + ((size_t)n * L2 + (size_t)chunk * 200) * KK + k;
    float acc = 0.0f;
    #pragma unroll 8
    for (int r = 0; r < 200; r++) acc += __ldg(base + (size_t)r * KK);
    d_part[n][chunk][k] = acc;
}

// -------------------------------------------- fused argmax + gather + ballot
// grid (NCHUNK, NN), block 256. Every block redundantly computes the (fully
// deterministic) argmax_k S0[k]*S1[k] from L2-resident partials, then gathers
// its 256 topic values and ballots the selection mask.
// top_k tie-break = lowest index first -> strict-greater, prefer lower index.
__global__ void tf_maskargmax_kernel(const float* __restrict__ topics) {
    int n = blockIdx.y;
    int t = threadIdx.x;
    __shared__ float bv[128];
    __shared__ int   bi[128];
    __shared__ int   s_ind;

    if (t < 128) {
        float best = -1.0f; int bidx = KK;
        if (t < KK) {
            float s0 = 0.f, s1 = 0.f;
            #pragma unroll 8
            for (int c = 0; c < 32; c++) s0 += d_part[n][c][t];
            #pragma unroll 8
            for (int c = 32; c < 64; c++) s1 += d_part[n][c][t];
            best = s0 * s1; bidx = t;
        }
        bv[t] = best; bi[t] = bidx;
    }
    __syncthreads();
    for (int s = 64; s > 0; s >>= 1) {
        if (t < s) {
            if (bv[t+s] > bv[t] || (bv[t+s] == bv[t] && bi[t+s] < bi[t])) {
                bv[t] = bv[t+s]; bi[t] = bi[t+s];
            }
        }
        __syncthreads();
    }
    if (t == 0) s_ind = bi[0];
    __syncthreads();

    int ind = s_ind;
    int l = blockIdx.x * 256 + t;
    float v = __ldg(topics + ((size_t)n * L2 + l) * KK + ind);
    unsigned ballot = __ballot_sync(0xFFFFFFFFu, v > 0.5f);
    if ((t & 31) == 0) d_bits[n][blockIdx.x * 8 + (t >> 5)] = ballot;
}

// -------------------------------------------- word-offset scan + inverse perm + out_mask
// grid NN, block 256. Exclusive prefix of per-word popcounts, total length,
// inverse permutation (dst rank -> src row), and the (n, 6400) output mask.
__global__ void tf_woff_kernel(float* __restrict__ out_mask) {
    int n = blockIdx.x;
    int t = threadIdx.x;
    __shared__ int ps[256];
    unsigned word = (t < NWORDS) ? d_bits[n][t] : 0u;
    int p = __popc(word);
    ps[t] = p;
    __syncthreads();
    for (int off = 1; off < 256; off <<= 1) {
        int v = (t >= off) ? ps[t - off] : 0;
        __syncthreads();
        ps[t] += v;
        __syncthreads();
    }
    int tot = ps[NWORDS - 1];
    if (t == 0) d_len[n] = tot;

    // inverse permutation: emit src row index for each set bit
    if (t < NWORDS) {
        int off = ps[t] - p;
        unsigned w = word;
        int base = t * 32;
        while (w) {
            int b = __ffs(w) - 1;
            d_srcrow[n][off++] = base + b;
            w &= w - 1;
        }
    }

    float* m = out_mask + (size_t)n * LL;
    #pragma unroll
    for (int l = t; l < LL; l += 256) m[l] = (l < tot) ? 1.0f : 0.0f;
}

// -------------------------------------------- gather compact + zero-fill
// grid (LL/8, NN), block (64,4). Each thread handles 2 independent dst rows
// (ty and ty+4) -> 2 in-flight loads, sequential streaming writes.
__global__ void tf_gather_kernel(const float* __restrict__ feat,
                                 float* __restrict__ out) {
    int n = blockIdx.y;
    int t = threadIdx.x;            // 64 lanes = one 1KB row
    int l1 = blockIdx.x * 8 + threadIdx.y;
    int l2 = l1 + 4;
    int len = d_len[n];

    bool v1 = l1 < len, v2 = l2 < len;
    int s1 = v1 ? d_srcrow[n][l1] : 0;     // L2-resident broadcast
    int s2 = v2 ? d_srcrow[n][l2] : 0;

    float4 a = make_float4(0.f, 0.f, 0.f, 0.f);
    float4 b = a;
    if (v1) a = ((const float4*)(feat + ((size_t)n*LL + s1) * CC))[t];
    if (v2) b = ((const float4*)(feat + ((size_t)n*LL + s2) * CC))[t];

    ((float4*)(out + ((size_t)n*LL + l1) * CC))[t] = a;
    ((float4*)(out + ((size_t)n*LL + l2) * CC))[t] = b;
}

extern "C" void kernel_launch(void* const* d_in, const int* in_sizes, int n_in,
                              void* d_out, int out_size) {
    const float* feat   = (const float*)d_in[0];   // (8, 6400, 256)
    const float* prob   = (const float*)d_in[1];   // (8, 12800, 100)
    const float* topics = (const float*)d_in[2];   // (8, 12800, 100)
    // d_in[3] = n_samples: only top-1 index is consumed -> argmax; unused here.

    float* out_feat = (float*)d_out;               // (8, 6400, 256)
    float* out_mask = out_feat + (size_t)NN*LL*CC; // (8, 6400)

    tf_reduce_kernel<<<dim3(64, NN), 128>>>(prob);
    tf_maskargmax_kernel<<<dim3(NCHUNK, NN), 256>>>(topics);
    tf_woff_kernel<<<NN, 256>>>(out_mask);
    tf_gather_kernel<<<dim3(LL/8, NN), dim3(64, 4)>>>(feat, out_feat);
}

// round 6
// speedup vs baseline: 1.4580x; 1.0272x over previous
#include <cuda_runtime.h>

#define NN 8
#define LL 6400
#define KK 100
#define CC 256
#define L2 (2*LL)
#define NCHUNK 25          // chunks of 256 l per n (mask kernel)
#define NWORDS (NCHUNK*8)  // 200 ballot words per n
#define RCH 128            // reduce chunks per n (100 rows each)

// Scratch (no allocations allowed) — fully rewritten every launch.
__device__ float    d_part[NN][RCH][KK];  // per-chunk column partial sums
__device__ unsigned d_bits[NN][NWORDS];   // selection bitmask, 32 l per word
__device__ int      d_srcrow[NN][LL];     // inverse perm: dst rank -> src row
__device__ int      d_len[NN];

// -------------------------------------------- column partial sums (no atomics)
// grid (RCH, NN), block 128. Chunk = 100 rows; chunks 0..63 = half 0, 64..127 = half 1.
__global__ void tf_reduce_kernel(const float* __restrict__ prob) {
    int n = blockIdx.y;
    int chunk = blockIdx.x;
    int k = threadIdx.x;
    if (k >= KK) return;
    const float* base = prob + ((size_t)n * L2 + (size_t)chunk * 100) * KK + k;
    float acc = 0.0f;
    #pragma unroll 10
    for (int r = 0; r < 100; r++) acc += __ldg(base + (size_t)r * KK);
    d_part[n][chunk][k] = acc;
}

// -------------------------------------------- fused argmax + gather + ballot
// grid (NCHUNK, NN), block 256. Every block redundantly computes the (fully
// deterministic) argmax_k S0[k]*S1[k] from L2-resident partials, then gathers
// its 256 topic values and ballots the selection mask.
// top_k tie-break = lowest index first -> strict-greater, prefer lower index.
__global__ void tf_maskargmax_kernel(const float* __restrict__ topics) {
    int n = blockIdx.y;
    int t = threadIdx.x;
    __shared__ float bv[128];
    __shared__ int   bi[128];
    __shared__ int   s_ind;

    if (t < 128) {
        float best = -1.0f; int bidx = KK;
        if (t < KK) {
            float s0 = 0.f, s1 = 0.f;
            #pragma unroll 8
            for (int c = 0; c < 64; c++) s0 += d_part[n][c][t];
            #pragma unroll 8
            for (int c = 64; c < 128; c++) s1 += d_part[n][c][t];
            best = s0 * s1; bidx = t;
        }
        bv[t] = best; bi[t] = bidx;
    }
    __syncthreads();
    for (int s = 64; s > 0; s >>= 1) {
        if (t < s) {
            if (bv[t+s] > bv[t] || (bv[t+s] == bv[t] && bi[t+s] < bi[t])) {
                bv[t] = bv[t+s]; bi[t] = bi[t+s];
            }
        }
        __syncthreads();
    }
    if (t == 0) s_ind = bi[0];
    __syncthreads();

    int ind = s_ind;
    int l = blockIdx.x * 256 + t;
    float v = __ldg(topics + ((size_t)n * L2 + l) * KK + ind);
    unsigned ballot = __ballot_sync(0xFFFFFFFFu, v > 0.5f);
    if ((t & 31) == 0) d_bits[n][blockIdx.x * 8 + (t >> 5)] = ballot;
}

// -------------------------------------------- word-offset scan + inverse perm + out_mask
// grid NN, block 256. Exclusive prefix of per-word popcounts, total length,
// inverse permutation (dst rank -> src row), and the (n, 6400) output mask.
__global__ void tf_woff_kernel(float* __restrict__ out_mask) {
    int n = blockIdx.x;
    int t = threadIdx.x;
    __shared__ int ps[256];
    unsigned word = (t < NWORDS) ? d_bits[n][t] : 0u;
    int p = __popc(word);
    ps[t] = p;
    __syncthreads();
    for (int off = 1; off < 256; off <<= 1) {
        int v = (t >= off) ? ps[t - off] : 0;
        __syncthreads();
        ps[t] += v;
        __syncthreads();
    }
    int tot = ps[NWORDS - 1];
    if (t == 0) d_len[n] = tot;

    // inverse permutation: emit src row index for each set bit
    if (t < NWORDS) {
        int off = ps[t] - p;
        unsigned w = word;
        int base = t * 32;
        while (w) {
            int b = __ffs(w) - 1;
            d_srcrow[n][off++] = base + b;
            w &= w - 1;
        }
    }

    float* m = out_mask + (size_t)n * LL;
    #pragma unroll
    for (int l = t; l < LL; l += 256) m[l] = (l < tot) ? 1.0f : 0.0f;
}

// -------------------------------------------- gather compact + zero-fill
// grid (LL/16, NN), block (64,4). Each thread handles 4 independent dst rows
// (ty + 4j) -> 4 in-flight loads, perfectly sequential streaming writes.
__global__ void tf_gather_kernel(const float* __restrict__ feat,
                                 float* __restrict__ out) {
    int n = blockIdx.y;
    int t = threadIdx.x;            // 64 lanes = one 1KB row
    int l0 = blockIdx.x * 16 + threadIdx.y;
    int len = d_len[n];

    int  l[4]; bool v[4]; int s[4]; float4 val[4];
    #pragma unroll
    for (int j = 0; j < 4; j++) {
        l[j] = l0 + 4*j;
        v[j] = l[j] < len;
        s[j] = v[j] ? d_srcrow[n][l[j]] : 0;   // L2-resident broadcast
        val[j] = make_float4(0.f, 0.f, 0.f, 0.f);
    }
    #pragma unroll
    for (int j = 0; j < 4; j++)
        if (v[j]) val[j] = ((const float4*)(feat + ((size_t)n*LL + s[j]) * CC))[t];
    #pragma unroll
    for (int j = 0; j < 4; j++)
        ((float4*)(out + ((size_t)n*LL + l[j]) * CC))[t] = val[j];
}

extern "C" void kernel_launch(void* const* d_in, const int* in_sizes, int n_in,
                              void* d_out, int out_size) {
    const float* feat   = (const float*)d_in[0];   // (8, 6400, 256)
    const float* prob   = (const float*)d_in[1];   // (8, 12800, 100)
    const float* topics = (const float*)d_in[2];   // (8, 12800, 100)
    // d_in[3] = n_samples: only top-1 index is consumed -> argmax; unused here.

    float* out_feat = (float*)d_out;               // (8, 6400, 256)
    float* out_mask = out_feat + (size_t)NN*LL*CC; // (8, 6400)

    tf_reduce_kernel<<<dim3(RCH, NN), 128>>>(prob);
    tf_maskargmax_kernel<<<dim3(NCHUNK, NN), 256>>>(topics);
    tf_woff_kernel<<<NN, 256>>>(out_mask);
    tf_gather_kernel<<<dim3(LL/16, NN), dim3(64, 4)>>>(feat, out_feat);
}

// round 9
// speedup vs baseline: 1.5811x; 1.0844x over previous
#include <cuda_runtime.h>

#define NN 8
#define LL 6400
#define KK 100
#define CC 256
#define L2 (2*LL)
#define NCHUNK 25          // chunks of 256 l per n (mask kernel)
#define NWORDS (NCHUNK*8)  // 200 ballot words per n
#define RCH 128            // reduce chunks per n (100 rows each)

// Scratch (no allocations allowed) — fully rewritten every launch.
// d_partT transposed: [n][k][chunk] so the argmax read is per-thread contiguous.
__device__ float    d_partT[NN][KK][RCH];
__device__ unsigned d_bits[NN][NWORDS];   // selection bitmask, 32 l per word
__device__ int      d_srcrow[NN][LL];     // inverse perm: dst rank -> src row
__device__ int      d_len[NN];
__device__ int      d_ticket[NN];         // last-block election; reset each launch

// -------------------------------------------- column partial sums (no atomics)
// grid (RCH, NN), block 128. Chunk = 100 rows; chunks 0..63 = half 0, 64..127 = half 1.
__global__ void tf_reduce_kernel(const float* __restrict__ prob) {
    int n = blockIdx.y;
    int chunk = blockIdx.x;
    int k = threadIdx.x;
    if (k >= KK) return;
    const float* base = prob + ((size_t)n * L2 + (size_t)chunk * 100) * KK + k;
    float acc = 0.0f;
    #pragma unroll 10
    for (int r = 0; r < 100; r++) acc += __ldg(base + (size_t)r * KK);
    d_partT[n][k][chunk] = acc;   // strided store, only 102K total — noise
}

// ---------------- fused argmax + gather + ballot + (last block) scan/perm/mask
// grid (NCHUNK, NN), block 256. Every block redundantly computes the (fully
// deterministic) argmax_k S0[k]*S1[k] — contiguous 512B read per thread.
// top_k tie-break = lowest index first -> strict-greater, prefer lower index.
// The LAST block per n (atomic ticket) performs the word scan, the inverse
// permutation, d_len, and the (n, 6400) output mask.
__global__ void tf_maskargmax_kernel(const float* __restrict__ topics,
                                     float* __restrict__ out_mask) {
    int n = blockIdx.y;
    int t = threadIdx.x;
    __shared__ float bv[128];
    __shared__ int   bi[128];
    __shared__ int   s_ind;
    __shared__ int   s_last;

    if (t < 128) {
        float best = -1.0f; int bidx = KK;
        if (t < KK) {
            const float4* p = (const float4*)&d_partT[n][t][0];   // 128 floats
            float s0 = 0.f, s1 = 0.f;
            #pragma unroll
            for (int c = 0; c < 16; c++) {
                float4 v = __ldg(p + c);
                s0 += (v.x + v.y) + (v.z + v.w);
            }
            #pragma unroll
            for (int c = 16; c < 32; c++) {
                float4 v = __ldg(p + c);
                s1 += (v.x + v.y) + (v.z + v.w);
            }
            best = s0 * s1; bidx = t;
        }
        bv[t] = best; bi[t] = bidx;
    }
    __syncthreads();
    for (int s = 64; s > 0; s >>= 1) {
        if (t < s) {
            if (bv[t+s] > bv[t] || (bv[t+s] == bv[t] && bi[t+s] < bi[t])) {
                bv[t] = bv[t+s]; bi[t] = bi[t+s];
            }
        }
        __syncthreads();
    }
    if (t == 0) s_ind = bi[0];
    __syncthreads();

    int ind = s_ind;
    int l = blockIdx.x * 256 + t;
    float v = __ldg(topics + ((size_t)n * L2 + l) * KK + ind);
    unsigned ballot = __ballot_sync(0xFFFFFFFFu, v > 0.5f);
    if ((t & 31) == 0) d_bits[n][blockIdx.x * 8 + (t >> 5)] = ballot;

    // ---- last-block election (release: fence before ticket) ----
    __threadfence();
    if (t == 0) s_last = atomicAdd(&d_ticket[n], 1);
    __syncthreads();
    if (s_last != NCHUNK - 1) return;
    __threadfence();               // acquire: all blocks' d_bits now visible

    // word-popcount exclusive scan over 200 words
    __shared__ int ps[256];
    unsigned word = (t < NWORDS) ? d_bits[n][t] : 0u;
    int p = __popc(word);
    ps[t] = p;
    __syncthreads();
    for (int off = 1; off < 256; off <<= 1) {
        int x = (t >= off) ? ps[t - off] : 0;
        __syncthreads();
        ps[t] += x;
        __syncthreads();
    }
    int tot = ps[NWORDS - 1];
    if (t == 0) { d_len[n] = tot; d_ticket[n] = 0; }   // reset for graph replay

    // inverse permutation: emit src row index for each set bit
    if (t < NWORDS) {
        int off = ps[t] - p;
        unsigned w = word;
        int base = t * 32;
        while (w) {
            int b = __ffs(w) - 1;
            d_srcrow[n][off++] = base + b;
            w &= w - 1;
        }
    }

    float* m = out_mask + (size_t)n * LL;
    #pragma unroll
    for (int i = t; i < LL; i += 256) m[i] = (i < tot) ? 1.0f : 0.0f;
}

// -------------------------------------------- gather compact + zero-fill
// grid (LL/16, NN), block (64,4). Each thread handles 4 independent dst rows
// (ty + 4j) -> 4 in-flight loads, perfectly sequential streaming writes.
__global__ void tf_gather_kernel(const float* __restrict__ feat,
                                 float* __restrict__ out) {
    int n = blockIdx.y;
    int t = threadIdx.x;            // 64 lanes = one 1KB row
    int l0 = blockIdx.x * 16 + threadIdx.y;
    int len = d_len[n];

    int  l[4]; bool v[4]; int s[4]; float4 val[4];
    #pragma unroll
    for (int j = 0; j < 4; j++) {
        l[j] = l0 + 4*j;
        v[j] = l[j] < len;
        s[j] = v[j] ? d_srcrow[n][l[j]] : 0;   // L2-resident broadcast
        val[j] = make_float4(0.f, 0.f, 0.f, 0.f);
    }
    #pragma unroll
    for (int j = 0; j < 4; j++)
        if (v[j]) val[j] = ((const float4*)(feat + ((size_t)n*LL + s[j]) * CC))[t];
    #pragma unroll
    for (int j = 0; j < 4; j++)
        ((float4*)(out + ((size_t)n*LL + l[j]) * CC))[t] = val[j];
}

extern "C" void kernel_launch(void* const* d_in, const int* in_sizes, int n_in,
                              void* d_out, int out_size) {
    const float* feat   = (const float*)d_in[0];   // (8, 6400, 256)
    const float* prob   = (const float*)d_in[1];   // (8, 12800, 100)
    const float* topics = (const float*)d_in[2];   // (8, 12800, 100)
    // d_in[3] = n_samples: only top-1 index is consumed -> argmax; unused here.

    float* out_feat = (float*)d_out;               // (8, 6400, 256)
    float* out_mask = out_feat + (size_t)NN*LL*CC; // (8, 6400)

    tf_reduce_kernel<<<dim3(RCH, NN), 128>>>(prob);
    tf_maskargmax_kernel<<<dim3(NCHUNK, NN), 256>>>(topics, out_mask);
    tf_gather_kernel<<<dim3(LL/16, NN), dim3(64, 4)>>>(feat, out_feat);
}

// round 10
// speedup vs baseline: 1.6789x; 1.0618x over previous
#include <cuda_runtime.h>

#define NN 8
#define LL 6400
#define KK 100
#define CC 256
#define L2 (2*LL)
#define NCHUNK 25          // chunks of 256 l per n (mask kernel)
#define NWORDS (NCHUNK*8)  // 200 ballot words per n
#define RCH 128            // reduce chunks per n (100 rows each)

// Scratch (no allocations allowed) — fully rewritten every launch.
// d_partT transposed: [n][k][chunk] so the argmax read is per-thread contiguous.
__device__ float    d_partT[NN][KK][RCH];
__device__ unsigned d_bits[NN][NWORDS];   // selection bitmask, 32 l per word
__device__ int      d_srcrow[NN][LL];     // inverse perm: dst rank -> src row
__device__ int      d_len[NN];
__device__ int      d_ticket[NN];         // last-block election; reset each launch

// -------------------------------------------- column partial sums, float4 stream
// grid (RCH, NN), block 256 (250 active). Chunk = 100 rows = 10000 floats =
// 2500 float4, streamed fully contiguously: thread t reads float4 index
// t + 250*it. Since 4*250 = 1000 ≡ 0 (mod 100), thread t's column phase
// k = 4*(t%25) is loop-invariant; rows advance by 10 per iteration.
__global__ void tf_reduce_kernel(const float* __restrict__ prob) {
    int n = blockIdx.y;
    int chunk = blockIdx.x;
    int t = threadIdx.x;
    const float4* base = (const float4*)(prob + ((size_t)n * L2 + (size_t)chunk * 100) * KK);

    float4 acc = make_float4(0.f, 0.f, 0.f, 0.f);
    if (t < 250) {
        #pragma unroll
        for (int it = 0; it < 10; it++) {
            float4 v = __ldg(base + t + it * 250);
            acc.x += v.x; acc.y += v.y; acc.z += v.z; acc.w += v.w;
        }
    }
    __shared__ float4 s[250];
    if (t < 250) s[t] = acc;
    __syncthreads();
    if (t < 25) {
        float4 a = s[t];
        #pragma unroll
        for (int g = 1; g < 10; g++) {
            float4 v = s[t + 25 * g];
            a.x += v.x; a.y += v.y; a.z += v.z; a.w += v.w;
        }
        int k = 4 * t;
        d_partT[n][k    ][chunk] = a.x;
        d_partT[n][k + 1][chunk] = a.y;
        d_partT[n][k + 2][chunk] = a.z;
        d_partT[n][k + 3][chunk] = a.w;
    }
}

// ---------------- fused argmax + gather + ballot + (last block) scan/perm/mask
// grid (NCHUNK, NN), block 256. Every block redundantly computes the (fully
// deterministic) argmax_k S0[k]*S1[k] — contiguous 512B read per thread.
// top_k tie-break = lowest index first -> strict-greater, prefer lower index.
// The LAST block per n (atomic ticket) performs the word scan, the inverse
// permutation, d_len, and the (n, 6400) output mask.
__global__ void tf_maskargmax_kernel(const float* __restrict__ topics,
                                     float* __restrict__ out_mask) {
    int n = blockIdx.y;
    int t = threadIdx.x;
    __shared__ float bv[128];
    __shared__ int   bi[128];
    __shared__ int   s_ind;
    __shared__ int   s_last;

    if (t < 128) {
        float best = -1.0f; int bidx = KK;
        if (t < KK) {
            const float4* p = (const float4*)&d_partT[n][t][0];   // 128 floats
            float s0 = 0.f, s1 = 0.f;
            #pragma unroll
            for (int c = 0; c < 16; c++) {
                float4 v = __ldg(p + c);
                s0 += (v.x + v.y) + (v.z + v.w);
            }
            #pragma unroll
            for (int c = 16; c < 32; c++) {
                float4 v = __ldg(p + c);
                s1 += (v.x + v.y) + (v.z + v.w);
            }
            best = s0 * s1; bidx = t;
        }
        bv[t] = best; bi[t] = bidx;
    }
    __syncthreads();
    for (int s = 64; s > 0; s >>= 1) {
        if (t < s) {
            if (bv[t+s] > bv[t] || (bv[t+s] == bv[t] && bi[t+s] < bi[t])) {
                bv[t] = bv[t+s]; bi[t] = bi[t+s];
            }
        }
        __syncthreads();
    }
    if (t == 0) s_ind = bi[0];
    __syncthreads();

    int ind = s_ind;
    int l = blockIdx.x * 256 + t;
    float v = __ldg(topics + ((size_t)n * L2 + l) * KK + ind);
    unsigned ballot = __ballot_sync(0xFFFFFFFFu, v > 0.5f);
    if ((t & 31) == 0) d_bits[n][blockIdx.x * 8 + (t >> 5)] = ballot;

    // ---- last-block election (release: fence before ticket) ----
    __threadfence();
    if (t == 0) s_last = atomicAdd(&d_ticket[n], 1);
    __syncthreads();
    if (s_last != NCHUNK - 1) return;
    __threadfence();               // acquire: all blocks' d_bits now visible

    // word-popcount exclusive scan over 200 words
    __shared__ int ps[256];
    unsigned word = (t < NWORDS) ? d_bits[n][t] : 0u;
    int p = __popc(word);
    ps[t] = p;
    __syncthreads();
    for (int off = 1; off < 256; off <<= 1) {
        int x = (t >= off) ? ps[t - off] : 0;
        __syncthreads();
        ps[t] += x;
        __syncthreads();
    }
    int tot = ps[NWORDS - 1];
    if (t == 0) { d_len[n] = tot; d_ticket[n] = 0; }   // reset for graph replay

    // inverse permutation: emit src row index for each set bit
    if (t < NWORDS) {
        int off = ps[t] - p;
        unsigned w = word;
        int base = t * 32;
        while (w) {
            int b = __ffs(w) - 1;
            d_srcrow[n][off++] = base + b;
            w &= w - 1;
        }
    }

    float* m = out_mask + (size_t)n * LL;
    #pragma unroll
    for (int i = t; i < LL; i += 256) m[i] = (i < tot) ? 1.0f : 0.0f;
}

// -------------------------------------------- gather compact + zero-fill
// grid (LL/16, NN), block (64,4). Each thread handles 4 independent dst rows
// (ty + 4j) -> 4 in-flight loads, perfectly sequential streaming writes.
__global__ void tf_gather_kernel(const float* __restrict__ feat,
                                 float* __restrict__ out) {
    int n = blockIdx.y;
    int t = threadIdx.x;            // 64 lanes = one 1KB row
    int l0 = blockIdx.x * 16 + threadIdx.y;
    int len = d_len[n];

    int  l[4]; bool v[4]; int s[4]; float4 val[4];
    #pragma unroll
    for (int j = 0; j < 4; j++) {
        l[j] = l0 + 4*j;
        v[j] = l[j] < len;
        s[j] = v[j] ? d_srcrow[n][l[j]] : 0;   // L2-resident broadcast
        val[j] = make_float4(0.f, 0.f, 0.f, 0.f);
    }
    #pragma unroll
    for (int j = 0; j < 4; j++)
        if (v[j]) val[j] = ((const float4*)(feat + ((size_t)n*LL + s[j]) * CC))[t];
    #pragma unroll
    for (int j = 0; j < 4; j++)
        ((float4*)(out + ((size_t)n*LL + l[j]) * CC))[t] = val[j];
}

extern "C" void kernel_launch(void* const* d_in, const int* in_sizes, int n_in,
                              void* d_out, int out_size) {
    const float* feat   = (const float*)d_in[0];   // (8, 6400, 256)
    const float* prob   = (const float*)d_in[1];   // (8, 12800, 100)
    const float* topics = (const float*)d_in[2];   // (8, 12800, 100)
    // d_in[3] = n_samples: only top-1 index is consumed -> argmax; unused here.

    float* out_feat = (float*)d_out;               // (8, 6400, 256)
    float* out_mask = out_feat + (size_t)NN*LL*CC; // (8, 6400)

    tf_reduce_kernel<<<dim3(RCH, NN), 256>>>(prob);
    tf_maskargmax_kernel<<<dim3(NCHUNK, NN), 256>>>(topics, out_mask);
    tf_gather_kernel<<<dim3(LL/16, NN), dim3(64, 4)>>>(feat, out_feat);
}